// round 11
// baseline (speedup 1.0000x reference)
#include <cuda_runtime.h>
#include <cuda_fp16.h>
#include <cstdint>

// ---------------------------------------------------------------------------
// Tri-plane sampling, channel-last fp16 scratch:
//   phase 1: fused transpose of 9 grids [32,R,R] -> [R*R,32] fp16 (66 MB).
//            __ldcs (evict-first) grid reads, float4-vectorized; scratch
//            written with L2::cache_hint evict-last policy => L2-pinned.
//   phase 2: 4 points/warp, 8 lanes/point. Row-pair gathers with evict-last
//            cache-hint policy (keep scratch resident); half2 lerps +
//            shfl_xor x-exchange; __stcs streaming output stores.
// ---------------------------------------------------------------------------

#define TOTAL_PX 1032192u   // 3*128^2 + 3*256^2 + 3*512^2
// 4 uint4 per pixel (32 x fp16); +4 pad for the x-edge row-pair overread
__device__ uint4 g_buf[TOTAL_PX * 4 + 4];   // 66 MB, 16B-aligned

__constant__ unsigned c_base_px[9] = {0u,      16384u,  32768u,
                                      49152u,  114688u, 180224u,
                                      245760u, 507904u, 770048u};
__constant__ int      c_npix[9]    = {16384, 16384, 16384,
                                      65536, 65536, 65536,
                                      262144, 262144, 262144};
// tile_start[i] = base_px[i] / 128  (128 pixels per block)
__constant__ int      c_tile_start[9] = {0, 128, 256,
                                         384, 896, 1408,
                                         1920, 3968, 6016};
#define TOTAL_TILES 8064    // TOTAL_PX / 128

struct GridPtrs { const float* g[9]; };

// L2 evict-last access policy (full-fraction)
__device__ __forceinline__ unsigned long long evict_last_policy() {
    unsigned long long pol;
    asm("createpolicy.fractional.L2::evict_last.b64 %0, 1.0;" : "=l"(pol));
    return pol;
}

// gather load with L2 retention hint
__device__ __forceinline__ uint4 ldg_keep(const uint4* p, unsigned long long pol) {
    uint4 v;
    asm("ld.global.nc.L2::cache_hint.v4.u32 {%0,%1,%2,%3}, [%4], %5;"
        : "=r"(v.x), "=r"(v.y), "=r"(v.z), "=r"(v.w) : "l"(p), "l"(pol));
    return v;
}

// scratch store with L2 retention hint
__device__ __forceinline__ void stg_keep(unsigned int* p, unsigned int w,
                                         unsigned long long pol) {
    asm volatile("st.global.L2::cache_hint.u32 [%0], %1, %2;"
                 :: "l"(p), "r"(w), "l"(pol));
}

__global__ void __launch_bounds__(256)
transpose_all(GridPtrs ptrs) {
    __shared__ float tile[128][33];   // stride 33
    const int b = blockIdx.x;

    int gi = 0;
    #pragma unroll
    for (int i = 1; i < 9; i++)
        if (b >= c_tile_start[i]) gi = i;

    const float* __restrict__ g = ptrs.g[gi];
    const int npix = c_npix[gi];
    const int pix0 = (b - c_tile_start[gi]) * 128;

    const int tx = threadIdx.x & 31;
    const int ty = threadIdx.x >> 5;   // warp id 0..7

    // phase 1: warp covers one channel's 128 px with 32 float4 loads
    // (evict-first: grids never re-read).
    #pragma unroll
    for (int c = ty; c < 32; c += 8) {
        const float4 v = __ldcs((const float4*)(g + (size_t)c * npix + pix0) + tx);
        tile[4 * tx + 0][c] = v.x;
        tile[4 * tx + 1][c] = v.y;
        tile[4 * tx + 2][c] = v.z;
        tile[4 * tx + 3][c] = v.w;
    }
    __syncthreads();

    // phase 2: warp writes 2 pixels/step as half2 -> 128B contiguous,
    // evict-last policy pins the scratch in L2 for the sampler.
    const unsigned long long pol = evict_last_policy();
    unsigned int* dst = (unsigned int*)g_buf + ((size_t)c_base_px[gi] + pix0) * 16;
    const int hl = tx & 15;
    #pragma unroll
    for (int s = 0; s < 8; s++) {
        const int pix = ty * 16 + s * 2 + (tx >> 4);
        const __half2 hh = __floats2half2_rn(tile[pix][2 * hl],
                                             tile[pix][2 * hl + 1]);
        stg_keep(dst + (size_t)pix * 16 + hl, *(const unsigned int*)&hh, pol);
    }
}

__global__ void __launch_bounds__(256)
sample_kernel(const float* __restrict__ pts, float* __restrict__ out, int n) {
    const int warp = (int)((blockIdx.x * 256u + threadIdx.x) >> 5);
    const int lane = threadIdx.x & 31;
    const int s    = lane & 7;            // 16B chunk of the 128B row-pair
    const int pt   = warp * 4 + (lane >> 3);
    const int ptc  = min(pt, n - 1);      // clamp so shuffles stay full-warp
    const bool live = (pt < n);

    const unsigned long long pol = evict_last_policy();

    const float vx = __ldg(pts + 3 * (size_t)ptc + 0);
    const float vy = __ldg(pts + 3 * (size_t)ptc + 1);
    const float vz = __ldg(pts + 3 * (size_t)ptc + 2);

    // p = (v - 1.6) * (-0.625) - 1
    const float px = (vx - 1.6f) * (-0.625f) - 1.0f;
    const float py = (vy - 1.6f) * (-0.625f) - 1.0f;
    const float pz = (vz - 1.6f) * (-0.625f) - 1.0f;

    const float cw[3] = {py, px, px};   // plane -> W coord
    const float ch[3] = {pz, pz, py};   // plane -> H coord

    const int Rs[3] = {128, 256, 512};
    const unsigned base_px[9] = {0u,      16384u,  32768u,
                                 49152u,  114688u, 180224u,
                                 245760u, 507904u, 770048u};

    const bool isR = (s >= 4);   // lane holds the x1 (right) corner after load
    float* outp = out + (size_t)ptc * 288 + 8 * (s & 3) + 4 * (s >> 2);

    #pragma unroll
    for (int l = 0; l < 3; l++) {
        const int   R   = Rs[l];
        const float Rm1 = (float)(R - 1);
        #pragma unroll
        for (int p = 0; p < 3; p++) {
            float x = (cw[p] + 1.0f) * 0.5f * Rm1;
            x = fminf(fmaxf(x, 0.0f), Rm1);
            float y = (ch[p] + 1.0f) * 0.5f * Rm1;
            y = fminf(fmaxf(y, 0.0f), Rm1);

            const float x0f = floorf(x), y0f = floorf(y);
            const float wx = x - x0f,    wy = y - y0f;
            const int x0 = (int)x0f,     y0 = (int)y0f;
            const int y1 = min(y0 + 1, R - 1);
            // x1 implicit: the 128B row-pair covers x0 and x0+1; at x0==R-1,
            // wx==0 so the (padded, in-bounds) overread has zero weight.

            const __half2 wy2  = __float2half2_rn(wy);
            const __half2 iwy2 = __float2half2_rn(1.0f - wy);
            const __half2 wx2  = __float2half2_rn(wx);
            const __half2 iwx2 = __float2half2_rn(1.0f - wx);

            const uint4* base = g_buf + ((size_t)base_px[l * 3 + p] << 2) + s;
            const uint4 a = ldg_keep(base + ((size_t)(y0 * R + x0) << 2), pol);
            const uint4 b = ldg_keep(base + ((size_t)(y1 * R + x0) << 2), pol);

            // y-lerp in half2: 8 channels of this lane's x-corner
            unsigned int ry[4];
            #pragma unroll
            for (int k = 0; k < 4; k++) {
                const unsigned int ua = (&a.x)[k], ub = (&b.x)[k];
                const __half2 v = __hfma2(*(const __half2*)&ub, wy2,
                                          __hmul2(*(const __half2*)&ua, iwy2));
                ry[k] = *(const unsigned int*)&v;
            }

            // exchange with partner x-corner (lane ^ 4), x-lerp in half2
            unsigned int res[4];
            #pragma unroll
            for (int k = 0; k < 4; k++) {
                const unsigned int o = __shfl_xor_sync(0xffffffffu, ry[k], 4);
                const unsigned int ulo = isR ? o     : ry[k];   // x0 corner
                const unsigned int uhi = isR ? ry[k] : o;       // x1 corner
                const __half2 v = __hfma2(*(const __half2*)&uhi, wx2,
                                          __hmul2(*(const __half2*)&ulo, iwx2));
                res[k] = *(const unsigned int*)&v;
            }

            // partners hold identical res; each lane converts/stores only its
            // half: words {0,1} for left lanes, {2,3} for right lanes.
            if (live) {
                const unsigned int w0 = isR ? res[2] : res[0];
                const unsigned int w1 = isR ? res[3] : res[1];
                const float2 f0 = __half22float2(*(const __half2*)&w0);
                const float2 f1 = __half22float2(*(const __half2*)&w1);
                float4 v; v.x = f0.x; v.y = f0.y; v.z = f1.x; v.w = f1.y;
                // streaming store: write-once output must not evict scratch
                __stcs((float4*)(outp + (l * 3 + p) * 32), v);
            }
        }
    }
}

extern "C" void kernel_launch(void* const* d_in, const int* in_sizes, int n_in,
                              void* d_out, int out_size) {
    const float* pts = (const float*)d_in[0];
    const int n = in_sizes[0] / 3;  // 300000 points

    GridPtrs ptrs;
    for (int i = 0; i < 9; i++) ptrs.g[i] = (const float*)d_in[1 + i];

    transpose_all<<<TOTAL_TILES, 256>>>(ptrs);

    // 4 points per warp, 8 warps per block -> 32 points per block
    const int blocks = (n + 31) / 32;
    sample_kernel<<<blocks, 256>>>(pts, (float*)d_out, n);
}

// round 12
// speedup vs baseline: 1.0059x; 1.0059x over previous
#include <cuda_runtime.h>
#include <cuda_fp16.h>
#include <cstdint>

// ---------------------------------------------------------------------------
// Tri-plane sampling, channel-last fp16 scratch:
//   phase 1: fused transpose (R9 measured-best): 128-px tiles, __ldcs scalar
//            grid reads, conflict-free smem, paired half2 stores.
//   phase 2: 4 points/warp, 8 lanes/point. Per LEVEL: compute 3 planes'
//            coords, issue all 6 row-pair gathers back-to-back (MLP=6),
//            then half2 lerps + shfl_xor x-exchange + __stcs stores.
// ---------------------------------------------------------------------------

#define TOTAL_PX 1032192u   // 3*128^2 + 3*256^2 + 3*512^2
// 4 uint4 per pixel (32 x fp16); +4 pad for the x-edge row-pair overread
__device__ uint4 g_buf[TOTAL_PX * 4 + 4];   // 66 MB, 16B-aligned

__constant__ unsigned c_base_px[9] = {0u,      16384u,  32768u,
                                      49152u,  114688u, 180224u,
                                      245760u, 507904u, 770048u};
__constant__ int      c_npix[9]    = {16384, 16384, 16384,
                                      65536, 65536, 65536,
                                      262144, 262144, 262144};
// tile_start[i] = base_px[i] / 128  (128 pixels per block)
__constant__ int      c_tile_start[9] = {0, 128, 256,
                                         384, 896, 1408,
                                         1920, 3968, 6016};
#define TOTAL_TILES 8064    // TOTAL_PX / 128

struct GridPtrs { const float* g[9]; };

// L2 evict-last access policy (full-fraction)
__device__ __forceinline__ unsigned long long evict_last_policy() {
    unsigned long long pol;
    asm("createpolicy.fractional.L2::evict_last.b64 %0, 1.0;" : "=l"(pol));
    return pol;
}

// gather load with L2 retention hint
__device__ __forceinline__ uint4 ldg_keep(const uint4* p, unsigned long long pol) {
    uint4 v;
    asm("ld.global.nc.L2::cache_hint.v4.u32 {%0,%1,%2,%3}, [%4], %5;"
        : "=r"(v.x), "=r"(v.y), "=r"(v.z), "=r"(v.w) : "l"(p), "l"(pol));
    return v;
}

__global__ void __launch_bounds__(256)
transpose_all(GridPtrs ptrs) {
    __shared__ float tile[128][33];   // stride 33: conflict-free both phases
    const int b = blockIdx.x;

    int gi = 0;
    #pragma unroll
    for (int i = 1; i < 9; i++)
        if (b >= c_tile_start[i]) gi = i;

    const float* __restrict__ g = ptrs.g[gi];
    const int npix = c_npix[gi];
    const int pix0 = (b - c_tile_start[gi]) * 128;

    const int tx = threadIdx.x & 31;
    const int ty = threadIdx.x >> 5;   // warp id 0..7

    #pragma unroll
    for (int c = ty; c < 32; c += 8) {
        const float* row = g + (size_t)c * npix + pix0;
        #pragma unroll
        for (int j = 0; j < 4; j++)
            tile[32 * j + tx][c] = __ldcs(row + 32 * j + tx);  // evict-first
    }
    __syncthreads();

    __half2* dst = (__half2*)g_buf + ((size_t)c_base_px[gi] + pix0) * 16;
    const int hl = tx & 15;
    #pragma unroll
    for (int s = 0; s < 8; s++) {
        const int pix = ty * 16 + s * 2 + (tx >> 4);
        const float a  = tile[pix][2 * hl];
        const float c2 = tile[pix][2 * hl + 1];
        dst[(size_t)pix * 16 + hl] = __floats2half2_rn(a, c2);
    }
}

__global__ void __launch_bounds__(256)
sample_kernel(const float* __restrict__ pts, float* __restrict__ out, int n) {
    const int warp = (int)((blockIdx.x * 256u + threadIdx.x) >> 5);
    const int lane = threadIdx.x & 31;
    const int s    = lane & 7;            // 16B chunk of the 128B row-pair
    const int pt   = warp * 4 + (lane >> 3);
    const int ptc  = min(pt, n - 1);      // clamp so shuffles stay full-warp
    const bool live = (pt < n);

    const unsigned long long pol = evict_last_policy();

    const float vx = __ldg(pts + 3 * (size_t)ptc + 0);
    const float vy = __ldg(pts + 3 * (size_t)ptc + 1);
    const float vz = __ldg(pts + 3 * (size_t)ptc + 2);

    // p = (v - 1.6) * (-0.625) - 1
    const float px = (vx - 1.6f) * (-0.625f) - 1.0f;
    const float py = (vy - 1.6f) * (-0.625f) - 1.0f;
    const float pz = (vz - 1.6f) * (-0.625f) - 1.0f;

    const float cw[3] = {py, px, px};   // plane -> W coord
    const float ch[3] = {pz, pz, py};   // plane -> H coord

    const int Rs[3] = {128, 256, 512};
    const unsigned base_px[9] = {0u,      16384u,  32768u,
                                 49152u,  114688u, 180224u,
                                 245760u, 507904u, 770048u};

    const bool isR = (s >= 4);   // lane holds the x1 (right) corner after load
    float* outp = out + (size_t)ptc * 288 + 8 * (s & 3) + 4 * (s >> 2);

    #pragma unroll
    for (int l = 0; l < 3; l++) {
        const int   R   = Rs[l];
        const float Rm1 = (float)(R - 1);

        // --- coords for all 3 planes of this level ---
        float wx[3], wy[3];
        const uint4* addr_a[3];
        const uint4* addr_b[3];
        #pragma unroll
        for (int p = 0; p < 3; p++) {
            float x = (cw[p] + 1.0f) * 0.5f * Rm1;
            x = fminf(fmaxf(x, 0.0f), Rm1);
            float y = (ch[p] + 1.0f) * 0.5f * Rm1;
            y = fminf(fmaxf(y, 0.0f), Rm1);

            const float x0f = floorf(x), y0f = floorf(y);
            wx[p] = x - x0f;
            wy[p] = y - y0f;
            const int x0 = (int)x0f, y0 = (int)y0f;
            const int y1 = min(y0 + 1, R - 1);
            // x1 implicit: row-pair load covers x0 and x0+1; at x0==R-1,
            // wx==0 so the (padded, in-bounds) overread has zero weight.

            const uint4* base = g_buf + ((size_t)base_px[l * 3 + p] << 2) + s;
            addr_a[p] = base + ((size_t)(y0 * R + x0) << 2);
            addr_b[p] = base + ((size_t)(y1 * R + x0) << 2);
        }

        // --- issue all 6 gathers back-to-back (MLP = 6) ---
        uint4 a[3], b[3];
        #pragma unroll
        for (int p = 0; p < 3; p++) a[p] = ldg_keep(addr_a[p], pol);
        #pragma unroll
        for (int p = 0; p < 3; p++) b[p] = ldg_keep(addr_b[p], pol);

        // --- lerp + exchange + store per plane ---
        #pragma unroll
        for (int p = 0; p < 3; p++) {
            const __half2 wy2  = __float2half2_rn(wy[p]);
            const __half2 iwy2 = __float2half2_rn(1.0f - wy[p]);
            const __half2 wx2  = __float2half2_rn(wx[p]);
            const __half2 iwx2 = __float2half2_rn(1.0f - wx[p]);

            unsigned int ry[4];
            #pragma unroll
            for (int k = 0; k < 4; k++) {
                const unsigned int ua = (&a[p].x)[k], ub = (&b[p].x)[k];
                const __half2 v = __hfma2(*(const __half2*)&ub, wy2,
                                          __hmul2(*(const __half2*)&ua, iwy2));
                ry[k] = *(const unsigned int*)&v;
            }

            unsigned int res[4];
            #pragma unroll
            for (int k = 0; k < 4; k++) {
                const unsigned int o = __shfl_xor_sync(0xffffffffu, ry[k], 4);
                const unsigned int ulo = isR ? o     : ry[k];   // x0 corner
                const unsigned int uhi = isR ? ry[k] : o;       // x1 corner
                const __half2 v = __hfma2(*(const __half2*)&uhi, wx2,
                                          __hmul2(*(const __half2*)&ulo, iwx2));
                res[k] = *(const unsigned int*)&v;
            }

            if (live) {
                const unsigned int w0 = isR ? res[2] : res[0];
                const unsigned int w1 = isR ? res[3] : res[1];
                const float2 f0 = __half22float2(*(const __half2*)&w0);
                const float2 f1 = __half22float2(*(const __half2*)&w1);
                float4 v; v.x = f0.x; v.y = f0.y; v.z = f1.x; v.w = f1.y;
                __stcs((float4*)(outp + (l * 3 + p) * 32), v);
            }
        }
    }
}

extern "C" void kernel_launch(void* const* d_in, const int* in_sizes, int n_in,
                              void* d_out, int out_size) {
    const float* pts = (const float*)d_in[0];
    const int n = in_sizes[0] / 3;  // 300000 points

    GridPtrs ptrs;
    for (int i = 0; i < 9; i++) ptrs.g[i] = (const float*)d_in[1 + i];

    transpose_all<<<TOTAL_TILES, 256>>>(ptrs);

    // 4 points per warp, 8 warps per block -> 32 points per block
    const int blocks = (n + 31) / 32;
    sample_kernel<<<blocks, 256>>>(pts, (float*)d_out, n);
}

// round 13
// speedup vs baseline: 1.0293x; 1.0232x over previous
#include <cuda_runtime.h>
#include <cuda_fp16.h>
#include <cstdint>

// ---------------------------------------------------------------------------
// Tri-plane sampling, channel-last fp16 scratch, LEVEL-PIPELINED:
//   The per-level transpose (t_l) and per-level sampler (s_l) only depend
//   pairwise (s_l needs t_l). Fork side streams in the captured graph:
//     default: t0 -> t1 -> t2
//     stream B: s0 (after t0), s2 (after t2)
//     stream C: s1 (after t1)
//   so transpose DRAM reads overlap sampler output writes.
// ---------------------------------------------------------------------------

#define TOTAL_PX 1032192u   // 3*128^2 + 3*256^2 + 3*512^2
// 4 uint4 per pixel (32 x fp16); +4 pad for the x-edge row-pair overread
__device__ uint4 g_buf[TOTAL_PX * 4 + 4];   // 66 MB, 16B-aligned

__constant__ unsigned c_base_px[9] = {0u,      16384u,  32768u,
                                      49152u,  114688u, 180224u,
                                      245760u, 507904u, 770048u};
__constant__ int      c_npix[9]    = {16384, 16384, 16384,
                                      65536, 65536, 65536,
                                      262144, 262144, 262144};
// tile_start[i] = base_px[i] / 128  (128 pixels per block)
__constant__ int      c_tile_start[9] = {0, 128, 256,
                                         384, 896, 1408,
                                         1920, 3968, 6016};

struct GridPtrs { const float* g[9]; };

__global__ void __launch_bounds__(256)
transpose_part(GridPtrs ptrs, int tile_bias) {
    __shared__ float tile[128][33];   // stride 33: conflict-free both phases
    const int b = blockIdx.x + tile_bias;

    int gi = 0;
    #pragma unroll
    for (int i = 1; i < 9; i++)
        if (b >= c_tile_start[i]) gi = i;

    const float* __restrict__ g = ptrs.g[gi];
    const int npix = c_npix[gi];
    const int pix0 = (b - c_tile_start[gi]) * 128;

    const int tx = threadIdx.x & 31;
    const int ty = threadIdx.x >> 5;   // warp id 0..7

    #pragma unroll
    for (int c = ty; c < 32; c += 8) {
        const float* row = g + (size_t)c * npix + pix0;
        #pragma unroll
        for (int j = 0; j < 4; j++)
            tile[32 * j + tx][c] = __ldcs(row + 32 * j + tx);  // evict-first
    }
    __syncthreads();

    __half2* dst = (__half2*)g_buf + ((size_t)c_base_px[gi] + pix0) * 16;
    const int hl = tx & 15;
    #pragma unroll
    for (int s = 0; s < 8; s++) {
        const int pix = ty * 16 + s * 2 + (tx >> 4);
        const float a  = tile[pix][2 * hl];
        const float c2 = tile[pix][2 * hl + 1];
        dst[(size_t)pix * 16 + hl] = __floats2half2_rn(a, c2);
    }
}

// One level (3 planes, resolution R, scratch pixel base B0, output col 96*LIDX)
template <int LIDX, int R, unsigned B0>
__global__ void __launch_bounds__(256)
sample_level(const float* __restrict__ pts, float* __restrict__ out, int n) {
    const int warp = (int)((blockIdx.x * 256u + threadIdx.x) >> 5);
    const int lane = threadIdx.x & 31;
    const int s    = lane & 7;            // 16B chunk of the 128B row-pair
    const int pt   = warp * 4 + (lane >> 3);
    const int ptc  = min(pt, n - 1);      // clamp so shuffles stay full-warp
    const bool live = (pt < n);

    const float vx = __ldg(pts + 3 * (size_t)ptc + 0);
    const float vy = __ldg(pts + 3 * (size_t)ptc + 1);
    const float vz = __ldg(pts + 3 * (size_t)ptc + 2);

    // p = (v - 1.6) * (-0.625) - 1
    const float px = (vx - 1.6f) * (-0.625f) - 1.0f;
    const float py = (vy - 1.6f) * (-0.625f) - 1.0f;
    const float pz = (vz - 1.6f) * (-0.625f) - 1.0f;

    const float cw[3] = {py, px, px};   // plane -> W coord
    const float ch[3] = {pz, pz, py};   // plane -> H coord

    const bool isR = (s >= 4);   // lane holds the x1 (right) corner after load
    float* outp = out + (size_t)ptc * 288 + LIDX * 96
                      + 8 * (s & 3) + 4 * (s >> 2);

    const float Rm1 = (float)(R - 1);
    #pragma unroll
    for (int p = 0; p < 3; p++) {
        float x = (cw[p] + 1.0f) * 0.5f * Rm1;
        x = fminf(fmaxf(x, 0.0f), Rm1);
        float y = (ch[p] + 1.0f) * 0.5f * Rm1;
        y = fminf(fmaxf(y, 0.0f), Rm1);

        const float x0f = floorf(x), y0f = floorf(y);
        const float wx = x - x0f,    wy = y - y0f;
        const int x0 = (int)x0f,     y0 = (int)y0f;
        const int y1 = min(y0 + 1, R - 1);
        // x1 implicit: the 128B row-pair covers x0 and x0+1; at x0==R-1,
        // wx==0 so the (padded, in-bounds) overread has zero weight.

        const __half2 wy2  = __float2half2_rn(wy);
        const __half2 iwy2 = __float2half2_rn(1.0f - wy);
        const __half2 wx2  = __float2half2_rn(wx);
        const __half2 iwx2 = __float2half2_rn(1.0f - wx);

        const uint4* base = g_buf + ((size_t)(B0 + (unsigned)p * R * R) << 2) + s;
        const uint4 a = __ldg(base + ((size_t)(y0 * R + x0) << 2));  // row y0
        const uint4 b = __ldg(base + ((size_t)(y1 * R + x0) << 2));  // row y1

        // y-lerp in half2: 8 channels of this lane's x-corner
        unsigned int ry[4];
        #pragma unroll
        for (int k = 0; k < 4; k++) {
            const unsigned int ua = (&a.x)[k], ub = (&b.x)[k];
            const __half2 v = __hfma2(*(const __half2*)&ub, wy2,
                                      __hmul2(*(const __half2*)&ua, iwy2));
            ry[k] = *(const unsigned int*)&v;
        }

        // exchange with partner x-corner (lane ^ 4), x-lerp in half2
        unsigned int res[4];
        #pragma unroll
        for (int k = 0; k < 4; k++) {
            const unsigned int o = __shfl_xor_sync(0xffffffffu, ry[k], 4);
            const unsigned int ulo = isR ? o     : ry[k];   // x0 corner
            const unsigned int uhi = isR ? ry[k] : o;       // x1 corner
            const __half2 v = __hfma2(*(const __half2*)&uhi, wx2,
                                      __hmul2(*(const __half2*)&ulo, iwx2));
            res[k] = *(const unsigned int*)&v;
        }

        if (live) {
            const unsigned int w0 = isR ? res[2] : res[0];
            const unsigned int w1 = isR ? res[3] : res[1];
            const float2 f0 = __half22float2(*(const __half2*)&w0);
            const float2 f1 = __half22float2(*(const __half2*)&w1);
            float4 v; v.x = f0.x; v.y = f0.y; v.z = f1.x; v.w = f1.y;
            __stcs((float4*)(outp + p * 32), v);   // streaming output store
        }
    }
}

extern "C" void kernel_launch(void* const* d_in, const int* in_sizes, int n_in,
                              void* d_out, int out_size) {
    const float* pts = (const float*)d_in[0];
    float* out = (float*)d_out;
    const int n = in_sizes[0] / 3;  // 300000 points

    GridPtrs ptrs;
    for (int i = 0; i < 9; i++) ptrs.g[i] = (const float*)d_in[1 + i];

    // one-time creation of side streams + events (resources, not work)
    static cudaStream_t sB = nullptr, sC = nullptr;
    static cudaEvent_t  eF0, eF1, eF2, eJB, eJC;
    if (sB == nullptr) {
        cudaStreamCreateWithFlags(&sB, cudaStreamNonBlocking);
        cudaStreamCreateWithFlags(&sC, cudaStreamNonBlocking);
        cudaEventCreateWithFlags(&eF0, cudaEventDisableTiming);
        cudaEventCreateWithFlags(&eF1, cudaEventDisableTiming);
        cudaEventCreateWithFlags(&eF2, cudaEventDisableTiming);
        cudaEventCreateWithFlags(&eJB, cudaEventDisableTiming);
        cudaEventCreateWithFlags(&eJC, cudaEventDisableTiming);
    }

    const int sblocks = (n + 31) / 32;   // 4 pts/warp, 8 warps/block

    // --- level 0: transpose tiles [0,384) then sample on stream B ---
    transpose_part<<<384, 256>>>(ptrs, 0);
    cudaEventRecord(eF0, 0);
    cudaStreamWaitEvent(sB, eF0, 0);
    sample_level<0, 128, 0u><<<sblocks, 256, 0, sB>>>(pts, out, n);

    // --- level 1: tiles [384,1920) then sample on stream C ---
    transpose_part<<<1536, 256>>>(ptrs, 384);
    cudaEventRecord(eF1, 0);
    cudaStreamWaitEvent(sC, eF1, 0);
    sample_level<1, 256, 49152u><<<sblocks, 256, 0, sC>>>(pts, out, n);

    // --- level 2: tiles [1920,8064) then sample on stream B ---
    transpose_part<<<6144, 256>>>(ptrs, 1920);
    cudaEventRecord(eF2, 0);
    cudaStreamWaitEvent(sB, eF2, 0);
    sample_level<2, 512, 245760u><<<sblocks, 256, 0, sB>>>(pts, out, n);

    // --- join side streams back into the capture (default) stream ---
    cudaEventRecord(eJB, sB);
    cudaEventRecord(eJC, sC);
    cudaStreamWaitEvent(0, eJB, 0);
    cudaStreamWaitEvent(0, eJC, 0);
}